// round 3
// baseline (speedup 1.0000x reference)
#include <cuda_runtime.h>

// Dis_model_60129542275: bilinear flow-warp resample.
// source [B,H,W,C=4] f32, flow [B,H,W,2] f32 (dy, dx per pixel), out [B,H,W,4] f32.
// warp = grid + flow; bilinear sample source at warp; zero output if warp center OOB.
// If the warp center is in-bounds, all 4 bilinear corner taps are in-bounds
// (floor/ceil of a value in [0, D-1] stays in [0, D-1]), so no per-tap guards.

static constexpr int Bn = 16;
static constexpr int Hn = 768;
static constexpr int Wn = 1024;
static constexpr int NPIX = Bn * Hn * Wn;

__global__ __launch_bounds__(256) void warp_bilinear_kernel(
    const float4* __restrict__ src,   // [B*H*W] float4 (C=4)
    const float2* __restrict__ flow,  // [B*H*W] float2 (dy, dx)
    float4* __restrict__ out)         // [B*H*W] float4
{
    int idx = blockIdx.x * blockDim.x + threadIdx.x;
    if (idx >= NPIX) return;

    int x = idx & (Wn - 1);          // Wn = 1024 = 2^10
    int rest = idx >> 10;
    int y = rest % Hn;
    int b = rest / Hn;

    float2 f = __ldg(flow + idx);
    float wy = (float)y + f.x;       // flow[...,0] is dy
    float wx = (float)x + f.y;       // flow[...,1] is dx

    bool ok = (wy >= 0.0f) & (wy <= (float)(Hn - 1)) &
              (wx >= 0.0f) & (wx <= (float)(Wn - 1));

    float4 r = make_float4(0.0f, 0.0f, 0.0f, 0.0f);
    if (ok) {
        float fy = floorf(wy);
        float fx = floorf(wx);
        int y0 = (int)fy;
        int x0 = (int)fx;
        int y1 = (int)ceilf(wy);
        int x1 = (int)ceilf(wx);

        float wr = wx - fx;          // weight right
        float wd = wy - fy;          // weight down
        float wl = 1.0f - wr;
        float wu = 1.0f - wd;

        const float4* sb = src + (size_t)b * (Hn * Wn);
        // Issue all 4 loads up front for MLP; scoreboard overlaps them.
        float4 t00 = __ldg(sb + y0 * Wn + x0);
        float4 t01 = __ldg(sb + y0 * Wn + x1);
        float4 t10 = __ldg(sb + y1 * Wn + x0);
        float4 t11 = __ldg(sb + y1 * Wn + x1);

        float w00 = wl * wu;
        float w01 = wr * wu;
        float w10 = wl * wd;
        float w11 = wr * wd;

        r.x = t00.x * w00 + t01.x * w01 + t10.x * w10 + t11.x * w11;
        r.y = t00.y * w00 + t01.y * w01 + t10.y * w10 + t11.y * w11;
        r.z = t00.z * w00 + t01.z * w01 + t10.z * w10 + t11.z * w11;
        r.w = t00.w * w00 + t01.w * w01 + t10.w * w10 + t11.w * w11;
    }
    out[idx] = r;   // d_out is poisoned; always write (zeros when masked)
}

extern "C" void kernel_launch(void* const* d_in, const int* in_sizes, int n_in,
                              void* d_out, int out_size)
{
    const float4* src  = (const float4*)d_in[0];   // source [16,768,1024,4]
    const float2* flow = (const float2*)d_in[1];   // flow   [16,768,1024,2]
    float4* out = (float4*)d_out;

    constexpr int threads = 256;
    constexpr int blocks = (NPIX + threads - 1) / threads;
    warp_bilinear_kernel<<<blocks, threads>>>(src, flow, out);
}

// round 4
// speedup vs baseline: 1.0033x; 1.0033x over previous
#include <cuda_runtime.h>

// Dis_model_60129542275: bilinear flow-warp resample.
// source [16,768,1024,4] f32, flow [16,768,1024,2] f32 (dy,dx), out [16,768,1024,4] f32.
//
// R3 version: 2 pixels per thread (strided by 256 within the block), all 8 tap
// loads made unconditional via coordinate clamping (mask folded into the row
// weights: weight 0 x finite value == 0, identical to the reference's masked
// result). Removes the divergent branch and doubles per-thread MLP so the
// L1TEX gather latency (the 83%-busy binding pipe last round) is fully hidden.

static constexpr int Bn = 16;
static constexpr int Hn = 768;
static constexpr int Wn = 1024;
static constexpr int HW = Hn * Wn;
static constexpr int NPIX = Bn * HW;
static constexpr int THREADS = 256;
static constexpr int PIX_PER_BLOCK = 2 * THREADS;   // 512

__global__ __launch_bounds__(THREADS) void warp_bilinear2_kernel(
    const float4* __restrict__ src,   // [B*H*W] float4 (C=4)
    const float2* __restrict__ flow,  // [B*H*W] float2 (dy, dx)
    float4* __restrict__ out)         // [B*H*W] float4
{
    const int p0 = blockIdx.x * PIX_PER_BLOCK + threadIdx.x;

    int   pidx[2];
    int   off[2][4];     // element offsets into src (32-bit, saves regs vs ptrs)
    float w[2][4];       // corner weights with OOB mask folded in

    #pragma unroll
    for (int j = 0; j < 2; ++j) {
        const int p = p0 + j * THREADS;
        pidx[j] = p;

        // decode p -> (b, y, x);  Wn = 1024 = 2^10
        const int x = p & (Wn - 1);
        const int r = p >> 10;
        const int b = (int)((unsigned)r / (unsigned)Hn);   // mul-shift
        const int y = r - b * Hn;

        const float2 f = __ldg(flow + p);
        const float wy = (float)y + f.x;   // flow[...,0] = dy
        const float wx = (float)x + f.y;   // flow[...,1] = dx

        // center-in-bounds mask (reference's mask_invalid)
        const float m = ((wy >= 0.0f) & (wy <= (float)(Hn - 1)) &
                         (wx >= 0.0f) & (wx <= (float)(Wn - 1))) ? 1.0f : 0.0f;

        const float fy = floorf(wy);
        const float fx = floorf(wx);
        const float wr = wx - fx;          // weight right
        const float wd = wy - fy;          // weight down
        const float wl = 1.0f - wr;
        float       wu = 1.0f - wd;
        float       wdm = wd;
        wu  *= m;                          // fold mask: result = m * bilinear
        wdm *= m;

        // clamp-safe tap coords. When in-bounds these equal the exact
        // floor/ceil taps (ceil==floor case has weight 0, value irrelevant).
        int x0 = min(max((int)fx, 0), Wn - 1);
        int y0 = min(max((int)fy, 0), Hn - 1);
        const int x1 = min(x0 + 1, Wn - 1);
        const int y1 = min(y0 + 1, Hn - 1);

        const int base = b * HW;
        off[j][0] = base + y0 * Wn + x0;
        off[j][1] = base + y0 * Wn + x1;
        off[j][2] = base + y1 * Wn + x0;
        off[j][3] = base + y1 * Wn + x1;

        w[j][0] = wl * wu;
        w[j][1] = wr * wu;
        w[j][2] = wl * wdm;
        w[j][3] = wr * wdm;
    }

    // Issue all 8 gathers back-to-back (unconditional -> max MLP).
    float4 t[2][4];
    #pragma unroll
    for (int j = 0; j < 2; ++j)
        #pragma unroll
        for (int k = 0; k < 4; ++k)
            t[j][k] = __ldg(src + off[j][k]);

    #pragma unroll
    for (int j = 0; j < 2; ++j) {
        float4 r4;
        r4.x = t[j][0].x * w[j][0] + t[j][1].x * w[j][1]
             + t[j][2].x * w[j][2] + t[j][3].x * w[j][3];
        r4.y = t[j][0].y * w[j][0] + t[j][1].y * w[j][1]
             + t[j][2].y * w[j][2] + t[j][3].y * w[j][3];
        r4.z = t[j][0].z * w[j][0] + t[j][1].z * w[j][1]
             + t[j][2].z * w[j][2] + t[j][3].z * w[j][3];
        r4.w = t[j][0].w * w[j][0] + t[j][1].w * w[j][1]
             + t[j][2].w * w[j][2] + t[j][3].w * w[j][3];
        out[pidx[j]] = r4;
    }
}

extern "C" void kernel_launch(void* const* d_in, const int* in_sizes, int n_in,
                              void* d_out, int out_size)
{
    const float4* src  = (const float4*)d_in[0];   // source [16,768,1024,4]
    const float2* flow = (const float2*)d_in[1];   // flow   [16,768,1024,2]
    float4* out = (float4*)d_out;

    static_assert(NPIX % PIX_PER_BLOCK == 0, "exact grid");
    constexpr int blocks = NPIX / PIX_PER_BLOCK;   // 24576
    warp_bilinear2_kernel<<<blocks, THREADS>>>(src, flow, out);
}

// round 5
// speedup vs baseline: 1.1460x; 1.1423x over previous
#include <cuda_runtime.h>

// Dis_model_60129542275: bilinear flow-warp resample.
// source [16,768,1024,4] f32, flow [16,768,1024,2] f32 (dy,dx), out [16,768,1024,4] f32.
//
// R4: lane-pair cooperative gathers. Adjacent lanes (2i, 2i+1) load the LEFT /
// RIGHT bilinear columns of the SAME pixel within one LDG.128 instruction, so
// the two 16B taps (x0, x0+1) coalesce into one L1 wavefront ~7/8 of the time.
// Cuts gather wavefronts/pixel from ~4 to ~2.25 (L1TEX was the 87%-saturated
// binding pipe). Partial sums are exchanged with one shfl.xor(1) per component.

static constexpr int Bn = 16;
static constexpr int Hn = 768;
static constexpr int Wn = 1024;
static constexpr int HW = Hn * Wn;
static constexpr int NPIX = Bn * HW;
static constexpr int THREADS = 256;

__global__ __launch_bounds__(THREADS) void warp_bilinear_pair_kernel(
    const float4* __restrict__ src,   // [B*H*W] float4 (C=4)
    const float2* __restrict__ flow,  // [B*H*W] float2 (dy, dx)
    float4* __restrict__ out)         // [B*H*W] float4
{
    const int p = blockIdx.x * THREADS + threadIdx.x;   // this lane's pixel
    const bool even = ((threadIdx.x & 1) == 0);
    const unsigned FULL = 0xffffffffu;

    // ---- per-pixel setup (owner lane computes everything for its pixel) ----
    const int x = p & (Wn - 1);                  // Wn = 2^10
    const int r = p >> 10;
    const int b = (int)((unsigned)r / (unsigned)Hn);
    const int y = r - b * Hn;

    const float2 f = __ldg(flow + p);
    const float wy = (float)y + f.x;             // flow[...,0] = dy
    const float wx = (float)x + f.y;             // flow[...,1] = dx

    const float m = ((wy >= 0.0f) & (wy <= (float)(Hn - 1)) &
                     (wx >= 0.0f) & (wx <= (float)(Wn - 1))) ? 1.0f : 0.0f;

    const float fy = floorf(wy);
    const float fx = floorf(wx);
    const float wrt = wx - fx;                   // right weight
    const float wdn = wy - fy;                   // down weight
    const float wlf = 1.0f - wrt;
    const float wup = (1.0f - wdn) * m;          // fold mask into row weights
    const float wdm = wdn * m;

    int x0 = min(max((int)fx, 0), Wn - 1);
    int y0 = min(max((int)fy, 0), Hn - 1);
    const int x1 = min(x0 + 1, Wn - 1);
    const int y1 = min(y0 + 1, Hn - 1);

    const int base = b * HW;
    const int o00 = base + y0 * Wn + x0;         // (y0, x0)
    const int o01 = base + y0 * Wn + x1;         // (y0, x1)
    const int o10 = base + y1 * Wn + x0;
    const int o11 = base + y1 * Wn + x1;

    const float w00 = wlf * wup;
    const float w01 = wrt * wup;
    const float w10 = wlf * wdm;
    const float w11 = wrt * wdm;

    // ---- exchange partner-pixel metadata (pair = lanes l, l^1) ----
    // Even lane loads LEFT column of both pixels; odd loads RIGHT column.
    const int   po00 = __shfl_xor_sync(FULL, o00, 1);  // partner (y0,x0) — used by even
    const int   po10 = __shfl_xor_sync(FULL, o10, 1);  //                — used by even
    const int   po01 = __shfl_xor_sync(FULL, o01, 1);  // partner (y0,x1) — used by odd
    const int   po11 = __shfl_xor_sync(FULL, o11, 1);  //                — used by odd
    const float pw00 = __shfl_xor_sync(FULL, w00, 1);
    const float pw10 = __shfl_xor_sync(FULL, w10, 1);
    const float pw01 = __shfl_xor_sync(FULL, w01, 1);
    const float pw11 = __shfl_xor_sync(FULL, w11, 1);

    // Instruction k gathers: k1/k2 = even-lane's pixel (rows y0,y1),
    // k3/k4 = odd-lane's pixel. Each lane supplies its own column parity,
    // so the pair's two addresses are 16B apart -> one L1 wavefront (p=7/8).
    const int a1 = even ? o00  : po01;
    const int a2 = even ? o10  : po11;
    const int a3 = even ? po00 : o01;
    const int a4 = even ? po10 : o11;

    const float g1 = even ? w00  : pw01;   // weight matching T1
    const float g2 = even ? w10  : pw11;
    const float g3 = even ? pw00 : w01;
    const float g4 = even ? pw10 : w11;

    const float4 T1 = __ldg(src + a1);
    const float4 T2 = __ldg(src + a2);
    const float4 T3 = __ldg(src + a3);
    const float4 T4 = __ldg(src + a4);

    // Column partials: pA = even-lane-pixel partial, pB = odd-lane-pixel partial.
    float4 pA, pB;
    pA.x = T1.x * g1 + T2.x * g2;  pB.x = T3.x * g3 + T4.x * g4;
    pA.y = T1.y * g1 + T2.y * g2;  pB.y = T3.y * g3 + T4.y * g4;
    pA.z = T1.z * g1 + T2.z * g2;  pB.z = T3.z * g3 + T4.z * g4;
    pA.w = T1.w * g1 + T2.w * g2;  pB.w = T3.w * g3 + T4.w * g4;

    // Each lane sends the partial of its PARTNER's pixel, receives the
    // missing column of its OWN pixel.
    float4 sendv;
    sendv.x = even ? pB.x : pA.x;
    sendv.y = even ? pB.y : pA.y;
    sendv.z = even ? pB.z : pA.z;
    sendv.w = even ? pB.w : pA.w;

    float4 recv;
    recv.x = __shfl_xor_sync(FULL, sendv.x, 1);
    recv.y = __shfl_xor_sync(FULL, sendv.y, 1);
    recv.z = __shfl_xor_sync(FULL, sendv.z, 1);
    recv.w = __shfl_xor_sync(FULL, sendv.w, 1);

    float4 res;
    res.x = (even ? pA.x : pB.x) + recv.x;
    res.y = (even ? pA.y : pB.y) + recv.y;
    res.z = (even ? pA.z : pB.z) + recv.z;
    res.w = (even ? pA.w : pB.w) + recv.w;

    out[p] = res;
}

extern "C" void kernel_launch(void* const* d_in, const int* in_sizes, int n_in,
                              void* d_out, int out_size)
{
    const float4* src  = (const float4*)d_in[0];   // source [16,768,1024,4]
    const float2* flow = (const float2*)d_in[1];   // flow   [16,768,1024,2]
    float4* out = (float4*)d_out;

    static_assert(NPIX % THREADS == 0, "exact grid");
    constexpr int blocks = NPIX / THREADS;         // 49152
    warp_bilinear_pair_kernel<<<blocks, THREADS>>>(src, flow, out);
}

// round 6
// speedup vs baseline: 1.2185x; 1.0633x over previous
#include <cuda_runtime.h>

// Dis_model_60129542275: bilinear flow-warp resample.
// source [16,768,1024,4] f32, flow [16,768,1024,2] f32 (dy,dx), out [16,768,1024,4] f32.
//
// R5: lane-pair cooperative gathers (even lane = LEFT column, odd = RIGHT column
// of both pair pixels, merging the 16B x-taps into one L1 wavefront 7/8 of the
// time) with ZERO metadata shuffles: the pair's two flows form one contiguous
// float4 which both lanes load (broadcast), and each lane redundantly computes
// the pair's metadata, keeping only its own column's offsets/weights.
// 2 pixels per thread (stride 256) -> 8 back-to-back gathers for MLP.
// Only 4 result shfls per pixel remain on the MIO pipe.

static constexpr int Bn = 16;
static constexpr int Hn = 768;
static constexpr int Wn = 1024;
static constexpr int HW = Hn * Wn;
static constexpr int NPIX = Bn * HW;
static constexpr int THREADS = 256;
static constexpr int PIX_PER_BLOCK = 2 * THREADS;   // 512

struct Meta { int off0, off1; float g0, g1; };

// Per-pixel, per-column metadata: offsets of (y0,xsel) and (y1,xsel) and the
// matching bilinear weights (mask folded in). xsel = x0 for even lanes, x1 for
// odd lanes. Clamped coords make the loads always-safe; zero weights kill any
// clamped/OOB contribution exactly (reference semantics).
__device__ __forceinline__ Meta setup_px(int p, float dy, float dx, bool even)
{
    const int x = p & (Wn - 1);                    // Wn = 2^10
    const int r = p >> 10;
    const int b = (int)((unsigned)r / (unsigned)Hn);
    const int y = r - b * Hn;

    const float wy = (float)y + dy;
    const float wx = (float)x + dx;

    const float m = ((wy >= 0.0f) & (wy <= (float)(Hn - 1)) &
                     (wx >= 0.0f) & (wx <= (float)(Wn - 1))) ? 1.0f : 0.0f;

    const float fy = floorf(wy);
    const float fx = floorf(wx);
    const float wrt = wx - fx;                     // right weight
    const float wdn = wy - fy;                     // down weight
    const float wcol = even ? (1.0f - wrt) : wrt;  // this lane's column weight
    const float wup = (1.0f - wdn) * m;
    const float wdm = wdn * m;

    const int x0 = min(max((int)fx, 0), Wn - 1);
    const int y0 = min(max((int)fy, 0), Hn - 1);
    const int xs = even ? x0 : min(x0 + 1, Wn - 1);
    const int y1 = min(y0 + 1, Hn - 1);

    Meta mt;
    const int base = b * HW + xs;
    mt.off0 = base + y0 * Wn;
    mt.off1 = base + y1 * Wn;
    mt.g0 = wcol * wup;
    mt.g1 = wcol * wdm;
    return mt;
}

__global__ __launch_bounds__(THREADS) void warp_bilinear_r5_kernel(
    const float4* __restrict__ src,    // [B*H*W] float4 (C=4)
    const float4* __restrict__ flow4,  // [B*H*W/2] float4 = 2 pixels' (dy,dx)
    float4* __restrict__ out)          // [B*H*W] float4
{
    const int tid = threadIdx.x;
    const bool even = ((tid & 1) == 0);
    const unsigned FULL = 0xffffffffu;
    const int p0 = blockIdx.x * PIX_PER_BLOCK + tid;

    Meta mA[2], mB[2];
    int  pj[2];

    #pragma unroll
    for (int j = 0; j < 2; ++j) {
        const int p = p0 + j * THREADS;
        pj[j] = p;
        const int pA = p & ~1;                       // even pixel of the pair
        // One float4 = (dyA, dxA, dyB, dxB); broadcast across the lane pair.
        const float4 f = __ldg(flow4 + (pA >> 1));
        mA[j] = setup_px(pA,     f.x, f.y, even);    // pixel A (even lane's own)
        mB[j] = setup_px(pA | 1, f.z, f.w, even);    // pixel B (odd lane's own)
    }

    // Issue all 8 gathers back-to-back. Within each instruction the lane pair's
    // two addresses are 16B apart -> one 128B wavefront with p=7/8.
    float4 TA0[2], TA1[2], TB0[2], TB1[2];
    #pragma unroll
    for (int j = 0; j < 2; ++j) {
        TA0[j] = __ldg(src + mA[j].off0);
        TA1[j] = __ldg(src + mA[j].off1);
        TB0[j] = __ldg(src + mB[j].off0);
        TB1[j] = __ldg(src + mB[j].off1);
    }

    #pragma unroll
    for (int j = 0; j < 2; ++j) {
        // This lane's column partial for each pair pixel.
        float4 pAc, pBc;
        pAc.x = TA0[j].x * mA[j].g0 + TA1[j].x * mA[j].g1;
        pAc.y = TA0[j].y * mA[j].g0 + TA1[j].y * mA[j].g1;
        pAc.z = TA0[j].z * mA[j].g0 + TA1[j].z * mA[j].g1;
        pAc.w = TA0[j].w * mA[j].g0 + TA1[j].w * mA[j].g1;
        pBc.x = TB0[j].x * mB[j].g0 + TB1[j].x * mB[j].g1;
        pBc.y = TB0[j].y * mB[j].g0 + TB1[j].y * mB[j].g1;
        pBc.z = TB0[j].z * mB[j].g0 + TB1[j].z * mB[j].g1;
        pBc.w = TB0[j].w * mB[j].g0 + TB1[j].w * mB[j].g1;

        // Exchange the partner pixel's partial; keep own pixel's.
        float4 sendv;
        sendv.x = even ? pBc.x : pAc.x;
        sendv.y = even ? pBc.y : pAc.y;
        sendv.z = even ? pBc.z : pAc.z;
        sendv.w = even ? pBc.w : pAc.w;

        float4 res;
        res.x = (even ? pAc.x : pBc.x) + __shfl_xor_sync(FULL, sendv.x, 1);
        res.y = (even ? pAc.y : pBc.y) + __shfl_xor_sync(FULL, sendv.y, 1);
        res.z = (even ? pAc.z : pBc.z) + __shfl_xor_sync(FULL, sendv.z, 1);
        res.w = (even ? pAc.w : pBc.w) + __shfl_xor_sync(FULL, sendv.w, 1);

        out[pj[j]] = res;   // own pixel: pj is even for even lanes (= pixel A)
    }
}

extern "C" void kernel_launch(void* const* d_in, const int* in_sizes, int n_in,
                              void* d_out, int out_size)
{
    const float4* src   = (const float4*)d_in[0];   // source [16,768,1024,4]
    const float4* flow4 = (const float4*)d_in[1];   // flow   [16,768,1024,2] as float4 pairs
    float4* out = (float4*)d_out;

    static_assert(NPIX % PIX_PER_BLOCK == 0, "exact grid");
    constexpr int blocks = NPIX / PIX_PER_BLOCK;    // 24576
    warp_bilinear_r5_kernel<<<blocks, THREADS>>>(src, flow4, out);
}

// round 7
// speedup vs baseline: 1.2406x; 1.0181x over previous
#include <cuda_runtime.h>

// Dis_model_60129542275: bilinear flow-warp resample.
// source [16,768,1024,4] f32, flow [16,768,1024,2] f32 (dy,dx), out [16,768,1024,4] f32.
//
// R6: identical structure to R5 (lane-pair cooperative column gathers, float4
// flow broadcast, 2 px/thread, 4 result shfls), with ONE change: the 8 gather
// loads use ld.global.cg (L2-cached, no L1 line fill). The gathers' intra-CTA
// L1 hit rate is low (taps scatter over ~10k lines per CTA), so L1 fills were
// pure crossbar waste on the 82%-pinned L1TEX pipe; real tap reuse lives in L2.

static constexpr int Bn = 16;
static constexpr int Hn = 768;
static constexpr int Wn = 1024;
static constexpr int HW = Hn * Wn;
static constexpr int NPIX = Bn * HW;
static constexpr int THREADS = 256;
static constexpr int PIX_PER_BLOCK = 2 * THREADS;   // 512

__device__ __forceinline__ float4 ldg_cg4(const float4* p) {
    float4 v;
    asm("ld.global.cg.v4.f32 {%0,%1,%2,%3}, [%4];"
        : "=f"(v.x), "=f"(v.y), "=f"(v.z), "=f"(v.w)
        : "l"(p));
    return v;
}

struct Meta { int off0, off1; float g0, g1; };

// Per-pixel, per-column metadata: offsets of (y0,xsel) and (y1,xsel) and the
// matching bilinear weights (mask folded in). xsel = x0 for even lanes, x1 for
// odd lanes. Clamped coords make the loads always-safe; zero weights kill any
// clamped/OOB contribution exactly (reference semantics).
__device__ __forceinline__ Meta setup_px(int p, float dy, float dx, bool even)
{
    const int x = p & (Wn - 1);                    // Wn = 2^10
    const int r = p >> 10;
    const int b = (int)((unsigned)r / (unsigned)Hn);
    const int y = r - b * Hn;

    const float wy = (float)y + dy;
    const float wx = (float)x + dx;

    const float m = ((wy >= 0.0f) & (wy <= (float)(Hn - 1)) &
                     (wx >= 0.0f) & (wx <= (float)(Wn - 1))) ? 1.0f : 0.0f;

    const float fy = floorf(wy);
    const float fx = floorf(wx);
    const float wrt = wx - fx;                     // right weight
    const float wdn = wy - fy;                     // down weight
    const float wcol = even ? (1.0f - wrt) : wrt;  // this lane's column weight
    const float wup = (1.0f - wdn) * m;
    const float wdm = wdn * m;

    const int x0 = min(max((int)fx, 0), Wn - 1);
    const int y0 = min(max((int)fy, 0), Hn - 1);
    const int xs = even ? x0 : min(x0 + 1, Wn - 1);
    const int y1 = min(y0 + 1, Hn - 1);

    Meta mt;
    const int base = b * HW + xs;
    mt.off0 = base + y0 * Wn;
    mt.off1 = base + y1 * Wn;
    mt.g0 = wcol * wup;
    mt.g1 = wcol * wdm;
    return mt;
}

__global__ __launch_bounds__(THREADS) void warp_bilinear_r6_kernel(
    const float4* __restrict__ src,    // [B*H*W] float4 (C=4)
    const float4* __restrict__ flow4,  // [B*H*W/2] float4 = 2 pixels' (dy,dx)
    float4* __restrict__ out)          // [B*H*W] float4
{
    const int tid = threadIdx.x;
    const bool even = ((tid & 1) == 0);
    const unsigned FULL = 0xffffffffu;
    const int p0 = blockIdx.x * PIX_PER_BLOCK + tid;

    Meta mA[2], mB[2];
    int  pj[2];

    #pragma unroll
    for (int j = 0; j < 2; ++j) {
        const int p = p0 + j * THREADS;
        pj[j] = p;
        const int pA = p & ~1;                       // even pixel of the pair
        // One float4 = (dyA, dxA, dyB, dxB); broadcast across the lane pair.
        const float4 f = __ldg(flow4 + (pA >> 1));
        mA[j] = setup_px(pA,     f.x, f.y, even);    // pixel A (even lane's own)
        mB[j] = setup_px(pA | 1, f.z, f.w, even);    // pixel B (odd lane's own)
    }

    // Issue all 8 gathers back-to-back via L1-bypassing .cg loads. Within each
    // instruction the lane pair's two addresses are 16B apart -> one 128B
    // wavefront with p=7/8, and no L1 line fill on miss.
    float4 TA0[2], TA1[2], TB0[2], TB1[2];
    #pragma unroll
    for (int j = 0; j < 2; ++j) {
        TA0[j] = ldg_cg4(src + mA[j].off0);
        TA1[j] = ldg_cg4(src + mA[j].off1);
        TB0[j] = ldg_cg4(src + mB[j].off0);
        TB1[j] = ldg_cg4(src + mB[j].off1);
    }

    #pragma unroll
    for (int j = 0; j < 2; ++j) {
        // This lane's column partial for each pair pixel.
        float4 pAc, pBc;
        pAc.x = TA0[j].x * mA[j].g0 + TA1[j].x * mA[j].g1;
        pAc.y = TA0[j].y * mA[j].g0 + TA1[j].y * mA[j].g1;
        pAc.z = TA0[j].z * mA[j].g0 + TA1[j].z * mA[j].g1;
        pAc.w = TA0[j].w * mA[j].g0 + TA1[j].w * mA[j].g1;
        pBc.x = TB0[j].x * mB[j].g0 + TB1[j].x * mB[j].g1;
        pBc.y = TB0[j].y * mB[j].g0 + TB1[j].y * mB[j].g1;
        pBc.z = TB0[j].z * mB[j].g0 + TB1[j].z * mB[j].g1;
        pBc.w = TB0[j].w * mB[j].g0 + TB1[j].w * mB[j].g1;

        // Exchange the partner pixel's partial; keep own pixel's.
        float4 sendv;
        sendv.x = even ? pBc.x : pAc.x;
        sendv.y = even ? pBc.y : pAc.y;
        sendv.z = even ? pBc.z : pAc.z;
        sendv.w = even ? pBc.w : pAc.w;

        float4 res;
        res.x = (even ? pAc.x : pBc.x) + __shfl_xor_sync(FULL, sendv.x, 1);
        res.y = (even ? pAc.y : pBc.y) + __shfl_xor_sync(FULL, sendv.y, 1);
        res.z = (even ? pAc.z : pBc.z) + __shfl_xor_sync(FULL, sendv.z, 1);
        res.w = (even ? pAc.w : pBc.w) + __shfl_xor_sync(FULL, sendv.w, 1);

        out[pj[j]] = res;   // own pixel: pj is even for even lanes (= pixel A)
    }
}

extern "C" void kernel_launch(void* const* d_in, const int* in_sizes, int n_in,
                              void* d_out, int out_size)
{
    const float4* src   = (const float4*)d_in[0];   // source [16,768,1024,4]
    const float4* flow4 = (const float4*)d_in[1];   // flow   [16,768,1024,2] as float4 pairs
    float4* out = (float4*)d_out;

    static_assert(NPIX % PIX_PER_BLOCK == 0, "exact grid");
    constexpr int blocks = NPIX / PIX_PER_BLOCK;    // 24576
    warp_bilinear_r6_kernel<<<blocks, THREADS>>>(src, flow4, out);
}